// round 1
// baseline (speedup 1.0000x reference)
#include <cuda_runtime.h>
#include <cuda_bf16.h>

// Problem constants
#define CELLS   4096
#define REGIONS 4096
#define NEMB    5
#define NINT    5

// Tiling
#define RT    256   // regions per block == threads per block (1 region per thread)
#define CB    32    // cells processed per block
#define CHUNK 4     // cell-rows staged to shared per sync

// floats per staged cell-row
#define ROW_F   (RT * NEMB)        // 1280 floats
#define ROW_F4  (ROW_F / 4)        // 320 float4

__global__ __launch_bounds__(RT)
void EmbeddingToExpression_45157286150935_kernel(
    const float* __restrict__ emb,    // [CELLS, REGIONS, NEMB]
    const int*   __restrict__ rix32,  // region_ix: int32 or int64 (detected)
    const float* __restrict__ w1,     // [N_REGIONS, NEMB, NINT]
    const float* __restrict__ b1,     // [N_REGIONS, NINT]
    const float* __restrict__ w2,     // [N_REGIONS, NINT, 1]
    const float* __restrict__ b2,     // [N_REGIONS, 1]
    float*       __restrict__ out)    // [CELLS, REGIONS]
{
    __shared__ float sh[CHUNK * ROW_F];   // 4 * 1280 floats = 20 KB

    const int tid = threadIdx.x;
    const int r   = blockIdx.x * RT + tid;   // this thread's region (fixed)
    const int a0  = blockIdx.y * CB;         // first cell for this block

    // --- region_ix dtype detection: int64 stores nonneg values < 20000, so
    // odd int32 words are all zero; for int32 data that's ~(1/20000)^4.
    const bool is64 = (rix32[1] == 0) & (rix32[3] == 0) &
                      (rix32[5] == 0) & (rix32[7] == 0);
    const int rix = is64 ? rix32[2 * r] : rix32[r];

    // --- gather per-region MLP params into registers (L2-resident tables)
    float W1[NEMB * NINT];
#pragma unroll
    for (int i = 0; i < NEMB * NINT; i++) W1[i] = __ldg(&w1[rix * (NEMB * NINT) + i]);
    float B1[NINT];
#pragma unroll
    for (int i = 0; i < NINT; i++) B1[i] = __ldg(&b1[rix * NINT + i]);
    float W2[NINT];
#pragma unroll
    for (int i = 0; i < NINT; i++) W2[i] = __ldg(&w2[rix * NINT + i]);
    const float B2 = __ldg(&b2[rix]);

    // float index of emb[a0, region_tile_start, 0]; tile start is 256-aligned
    // so this is a multiple of 1280 -> 16B aligned for float4.
    const size_t row_base0 = ((size_t)a0 * REGIONS + (size_t)blockIdx.x * RT) * NEMB;
    const size_t row_stride = (size_t)REGIONS * NEMB;   // 20480 floats between cells

    for (int ac = 0; ac < CB; ac += CHUNK) {
        __syncthreads();   // protect shared from previous compute phase
        // --- stage CHUNK cell-rows (CHUNK*320 float4) fully coalesced
#pragma unroll
        for (int i = 0; i < (CHUNK * ROW_F4) / RT; i++) {   // 5 iterations
            int flat = i * RT + tid;             // 0..1279
            int row  = flat / ROW_F4;            // 0..3
            int col  = flat - row * ROW_F4;      // 0..319
            size_t g = row_base0 + (size_t)(ac + row) * row_stride + (size_t)col * 4;
            ((float4*)sh)[flat] = __ldg((const float4*)(emb + g));
        }
        __syncthreads();

        // --- compute CHUNK outputs for this thread's region
#pragma unroll
        for (int row = 0; row < CHUNK; row++) {
            const float* xs = &sh[row * ROW_F + tid * NEMB];  // stride-5: bank-conflict-free
            const float x0 = xs[0], x1 = xs[1], x2 = xs[2], x3 = xs[3], x4 = xs[4];
            float o = B2;
#pragma unroll
            for (int d = 0; d < NINT; d++) {
                float acc = B1[d]
                          + x0 * W1[0 * NINT + d]
                          + x1 * W1[1 * NINT + d]
                          + x2 * W1[2 * NINT + d]
                          + x3 * W1[3 * NINT + d]
                          + x4 * W1[4 * NINT + d];
                float h = 1.0f / (1.0f + __expf(-acc));
                o += h * W2[d];
            }
            const int a = a0 + ac + row;
            out[(size_t)a * REGIONS + r] = o;
        }
    }
}

extern "C" void kernel_launch(void* const* d_in, const int* in_sizes, int n_in,
                              void* d_out, int out_size)
{
    const float* emb   = (const float*)d_in[0];
    const int*   rix   = (const int*)  d_in[1];
    const float* w1    = (const float*)d_in[2];
    const float* b1    = (const float*)d_in[3];
    const float* w2    = (const float*)d_in[4];
    const float* b2    = (const float*)d_in[5];
    float*       outp  = (float*)d_out;

    dim3 grid(REGIONS / RT, CELLS / CB);   // (16, 128) = 2048 blocks
    EmbeddingToExpression_45157286150935_kernel<<<grid, RT>>>(
        emb, rix, w1, b1, w2, b2, outp);
}

// round 2
// speedup vs baseline: 1.7282x; 1.7282x over previous
#include <cuda_runtime.h>
#include <cuda_bf16.h>

// Problem constants
#define CELLS   4096
#define REGIONS 4096
#define NEMB    5
#define NINT    5

// Tiling
#define RT    256   // regions per block == threads per block (1 region per thread)
#define CB    32    // cells processed per block
#define CHUNK 4     // cell-rows staged per pipeline stage

// floats per staged cell-row
#define ROW_F    (RT * NEMB)        // 1280 floats
#define ROW_F4   (ROW_F / 4)        // 320 float4
#define STAGE_F4 (CHUNK * ROW_F4)   // 1280 float4 per stage
#define NSTAGES  (CB / CHUNK)       // 8 pipeline stages

__device__ __forceinline__ unsigned smem_u32(const void* p) {
    unsigned a;
    asm("{ .reg .u64 t; cvta.to.shared.u64 t, %1; cvt.u32.u64 %0, t; }"
        : "=r"(a) : "l"(p));
    return a;
}

__global__ __launch_bounds__(RT, 4)
void EmbeddingToExpression_45157286150935_kernel(
    const float* __restrict__ emb,    // [CELLS, REGIONS, NEMB]
    const int*   __restrict__ rix32,  // region_ix: int32 or int64 (detected)
    const float* __restrict__ w1,     // [N_REGIONS, NEMB, NINT]
    const float* __restrict__ b1,     // [N_REGIONS, NINT]
    const float* __restrict__ w2,     // [N_REGIONS, NINT, 1]
    const float* __restrict__ b2,     // [N_REGIONS, 1]
    float*       __restrict__ out)    // [CELLS, REGIONS]
{
    __shared__ float sh[2][CHUNK * ROW_F];   // 2 x 20 KB

    const int tid = threadIdx.x;
    const int r   = blockIdx.x * RT + tid;   // this thread's region (fixed)
    const int a0  = blockIdx.y * CB;         // first cell for this block

    // --- region_ix dtype detection: int64 values < 20000 -> odd words all 0
    const bool is64 = (rix32[1] == 0) & (rix32[3] == 0) &
                      (rix32[5] == 0) & (rix32[7] == 0);
    const int rix = is64 ? rix32[2 * r] : rix32[r];

    // --- gather per-region MLP params into registers (tables are L2-resident)
    float W1[NEMB * NINT];
#pragma unroll
    for (int i = 0; i < NEMB * NINT; i++) W1[i] = __ldg(&w1[rix * (NEMB * NINT) + i]);
    float B1[NINT];
#pragma unroll
    for (int i = 0; i < NINT; i++) B1[i] = __ldg(&b1[rix * NINT + i]);
    float W2[NINT];
#pragma unroll
    for (int i = 0; i < NINT; i++) W2[i] = __ldg(&w2[rix * NINT + i]);
    const float B2 = __ldg(&b2[rix]);

    // float index of emb[a0, region_tile_start, 0]; 256-aligned tile start ->
    // multiple of 1280 floats -> 16B aligned for cp.async 16.
    const size_t row_base0  = ((size_t)a0 * REGIONS + (size_t)blockIdx.x * RT) * NEMB;
    const size_t row_stride = (size_t)REGIONS * NEMB;   // 20480 floats between cells

    // stage k: copy CHUNK cell-rows (1280 float4) into sh[buf] via cp.async
    auto stage = [&](int k, int buf) {
        unsigned sbase = smem_u32(&sh[buf][0]);
#pragma unroll
        for (int i = 0; i < STAGE_F4 / RT; i++) {   // 5 x cp.async.16 per thread
            int flat = i * RT + tid;                // 0..1279
            int row  = flat / ROW_F4;               // 0..3
            int col  = flat - row * ROW_F4;         // 0..319
            const float* g = emb + row_base0
                           + (size_t)(k * CHUNK + row) * row_stride
                           + (size_t)col * 4;
            unsigned s = sbase + (unsigned)flat * 16u;
            asm volatile("cp.async.ca.shared.global [%0], [%1], 16;"
                         :: "r"(s), "l"(g));
        }
        asm volatile("cp.async.commit_group;");
    };

    // --- software pipeline: depth-2 double buffer
    stage(0, 0);

#pragma unroll 1
    for (int k = 0; k < NSTAGES; k++) {
        const int cur = k & 1;
        if (k + 1 < NSTAGES) stage(k + 1, cur ^ 1);

        if (k + 1 < NSTAGES) asm volatile("cp.async.wait_group 1;");
        else                 asm volatile("cp.async.wait_group 0;");
        __syncthreads();   // staged data visible to all threads

        // --- compute CHUNK outputs for this thread's region
#pragma unroll
        for (int row = 0; row < CHUNK; row++) {
            const float* xs = &sh[cur][row * ROW_F + tid * NEMB]; // stride-5: conflict-free
            const float x0 = xs[0], x1 = xs[1], x2 = xs[2], x3 = xs[3], x4 = xs[4];
            float o = B2;
#pragma unroll
            for (int d = 0; d < NINT; d++) {
                float acc = B1[d]
                          + x0 * W1[0 * NINT + d]
                          + x1 * W1[1 * NINT + d]
                          + x2 * W1[2 * NINT + d]
                          + x3 * W1[3 * NINT + d]
                          + x4 * W1[4 * NINT + d];
                // sigmoid(x) = 0.5*tanh(0.5x) + 0.5  -> single MUFU.TANH
                float t;
                asm("tanh.approx.f32 %0, %1;" : "=f"(t) : "f"(0.5f * acc));
                o = fmaf(0.5f * t + 0.5f, W2[d], o);
            }
            const int a = a0 + k * CHUNK + row;
            out[(size_t)a * REGIONS + r] = o;
        }
        __syncthreads();   // all reads of sh[cur] done before next stage overwrites it
    }
}

extern "C" void kernel_launch(void* const* d_in, const int* in_sizes, int n_in,
                              void* d_out, int out_size)
{
    const float* emb  = (const float*)d_in[0];
    const int*   rix  = (const int*)  d_in[1];
    const float* w1   = (const float*)d_in[2];
    const float* b1   = (const float*)d_in[3];
    const float* w2   = (const float*)d_in[4];
    const float* b2   = (const float*)d_in[5];
    float*       outp = (float*)d_out;

    dim3 grid(REGIONS / RT, CELLS / CB);   // (16, 128) = 2048 blocks
    EmbeddingToExpression_45157286150935_kernel<<<grid, RT>>>(
        emb, rix, w1, b1, w2, b2, outp);
}